// round 5
// baseline (speedup 1.0000x reference)
#include <cuda_runtime.h>
#include <cstdint>

// Shapes (fixed by the problem)
#define B_ 2
#define S_ 1024
#define H_ 512
#define A_ 128

#define CTAS_PER_B 74            // per-batch attn CTAs, 13-14 rows each
#define MAXR 16
#define TJ 128
#define NT 8                     // S_/TJ tiles

// ---------------- scratch (no allocation allowed) ----------------
__device__ float g_wx [B_ * S_ * A_];        // [m=b*S+s][a]  row-major (1 MB)
__device__ float g_uxt[B_ * A_ * S_];        // [b][a][s]     a-major / transposed (1 MB)
__device__ float g_colsum[B_ * S_];

// ---- streams/events created once at static init (host-side resources only)
struct HxStreams {
    cudaStream_t s2;
    cudaEvent_t e_g0, e_a0;
    HxStreams() {
        cudaStreamCreateWithFlags(&s2, cudaStreamNonBlocking);
        cudaEventCreateWithFlags(&e_g0, cudaEventDisableTiming);
        cudaEventCreateWithFlags(&e_a0, cudaEventDisableTiming);
    }
};
static HxStreams hx;

__device__ __forceinline__ float tanh_fast(float x) {
    float y;
    asm("tanh.approx.f32 %0, %1;" : "=f"(y) : "f"(x));
    return y;
}

__device__ __forceinline__ void cp16(float* dst_smem, const float* src) {
    uint32_t d = (uint32_t)__cvta_generic_to_shared(dst_smem);
    asm volatile("cp.async.cg.shared.global [%0], [%1], 16;\n" :: "r"(d), "l"(src));
}
#define CP_COMMIT() asm volatile("cp.async.commit_group;\n")
#define CP_WAIT(N)  asm volatile("cp.async.wait_group %0;\n" :: "n"(N))

// ---------------- kernel 1 (per batch): wx/uxt gemm + fused zeroing ----------------
// BM=32, BN=64, BK=16; grid (32, 4): by 0,1 -> w cols 0..127 ; by 2,3 -> u cols
#define BM 32
#define BN 64
#define BK 16
__global__ __launch_bounds__(256) void gemm_wxux_b(
    const float* __restrict__ lstm, const float* __restrict__ w, const float* __restrict__ u,
    float* __restrict__ ctx, int b)
{
    __shared__ float As[BK][BM];
    __shared__ float Bs[BK][BN];
    int tid = threadIdx.x;

    // fused zeroing of this batch's colsum + ctx (block (0,0) only)
    if (blockIdx.x == 0 && blockIdx.y == 0) {
        for (int t = tid; t < S_; t += 256) g_colsum[b * S_ + t] = 0.0f;
        if (tid < H_ / 2) {
            ctx[b * H_ + tid] = 0.0f;
            ctx[b * H_ + 256 + tid] = 0.0f;
        }
    }

    const float* lstm_b = lstm + (size_t)b * S_ * H_;
    int m0 = blockIdx.x * BM;                  // 0..992 (within batch)
    int n0 = blockIdx.y * BN;                  // 0,64 -> w ; 128,192 -> u
    const float* bsrc = (n0 < A_) ? (w + n0) : (u + (n0 - A_));

    int tm = (tid >> 4) * 2;                   // 0..30
    int tn = (tid & 15) * 4;                   // 0..60
    int la_m = tid >> 2;                       // 0..63 (only tid<128 used)
    int la_k = (tid & 3) * 4;
    int lb_k = tid >> 4;                       // 0..15
    int lb_n = (tid & 15) * 4;

    float acc[2][4];
#pragma unroll
    for (int i = 0; i < 2; i++)
#pragma unroll
        for (int j = 0; j < 4; j++) acc[i][j] = 0.0f;

    for (int k0 = 0; k0 < H_; k0 += BK) {
        float4 av = make_float4(0.f, 0.f, 0.f, 0.f);
        if (tid < 128)
            av = *(const float4*)(lstm_b + (size_t)(m0 + la_m) * H_ + k0 + la_k);
        float4 bv = *(const float4*)(bsrc + (size_t)(k0 + lb_k) * A_ + lb_n);
        __syncthreads();
        if (tid < 128) {
            As[la_k + 0][la_m] = av.x;
            As[la_k + 1][la_m] = av.y;
            As[la_k + 2][la_m] = av.z;
            As[la_k + 3][la_m] = av.w;
        }
        *(float4*)&Bs[lb_k][lb_n] = bv;
        __syncthreads();
#pragma unroll
        for (int kk = 0; kk < BK; kk++) {
            float a0 = As[kk][tm], a1 = As[kk][tm + 1];
            float4 b4 = *(const float4*)&Bs[kk][tn];
            acc[0][0] = fmaf(a0, b4.x, acc[0][0]);
            acc[0][1] = fmaf(a0, b4.y, acc[0][1]);
            acc[0][2] = fmaf(a0, b4.z, acc[0][2]);
            acc[0][3] = fmaf(a0, b4.w, acc[0][3]);
            acc[1][0] = fmaf(a1, b4.x, acc[1][0]);
            acc[1][1] = fmaf(a1, b4.y, acc[1][1]);
            acc[1][2] = fmaf(a1, b4.z, acc[1][2]);
            acc[1][3] = fmaf(a1, b4.w, acc[1][3]);
        }
    }

    if (n0 < A_) {
        // wx: row-major [b*S+m][a]
#pragma unroll
        for (int i = 0; i < 2; i++) {
            float4 o = make_float4(acc[i][0], acc[i][1], acc[i][2], acc[i][3]);
            *(float4*)(g_wx + (size_t)(b * S_ + m0 + tm + i) * A_ + n0 + tn) = o;
        }
    } else {
        // ux: transposed -> g_uxt[b][a][s]
        int a0 = (n0 - A_) + tn;
        int s0 = m0 + tm;
        float* base = g_uxt + (size_t)b * A_ * S_;
#pragma unroll
        for (int j = 0; j < 4; j++) {
            float2 o = make_float2(acc[0][j], acc[1][j]);
            *(float2*)(base + (size_t)(a0 + j) * S_ + s0) = o;
        }
    }
}

// ---------------- kernel 2 (per batch): e = tanh-sum, reg softmax, attn + colsum ----------------
// dyn smem: wx_s[16][128] + ux double buffer 2*[128][TJ] + v_s[128]  ~ 139.8 KB
__global__ __launch_bounds__(512) void attn_e_kernel(
    const float* __restrict__ v, float* __restrict__ attn_out, int b)
{
    extern __shared__ float sm[];
    float* wx_s = sm;                          // MAXR*128
    float* ux0  = wx_s + MAXR * A_;            // 128*TJ buffer 0
    float* ux1  = ux0 + A_ * TJ;               // 128*TJ buffer 1
    float* v_s  = ux1 + A_ * TJ;               // 128

    int tid  = threadIdx.x;
    int warp = tid >> 5;
    int lane = tid & 31;
    int t_   = blockIdx.x;                     // 0..73
    int i0   = (S_ * t_) / CTAS_PER_B;
    int i1   = (S_ * (t_ + 1)) / CTAS_PER_B;
    int nr   = i1 - i0;                        // 13 or 14

    const float* uxt_b = g_uxt + (size_t)b * A_ * S_;
    int pa = tid >> 5, pc = tid & 31;          // prefetch coords: 8 rows per thread

#pragma unroll
    for (int k = 0; k < 8; k++)
        cp16(ux0 + (pa + 16 * k) * TJ + 4 * pc, uxt_b + (size_t)(pa + 16 * k) * S_ + 4 * pc);
    CP_COMMIT();

    for (int x = tid; x < nr * (A_ / 4); x += 512) {
        int r = x >> 5, c = x & 31;
        *(float4*)(wx_s + r * A_ + 4 * c) =
            *(const float4*)(g_wx + (size_t)(b * S_ + i0 + r) * A_ + 4 * c);
    }
    if (tid < 32) ((float4*)v_s)[tid] = ((const float4*)v)[tid];

    bool active = (warp < nr);
    float er[4 * NT];

#pragma unroll
    for (int t = 0; t < NT; t++) {
        float* cur = (t & 1) ? ux1 : ux0;
        if (t + 1 < NT) {
            float* nxt = ((t + 1) & 1) ? ux1 : ux0;
            const float* src = uxt_b + (size_t)(t + 1) * TJ;
#pragma unroll
            for (int k = 0; k < 8; k++)
                cp16(nxt + (pa + 16 * k) * TJ + 4 * pc, src + (size_t)(pa + 16 * k) * S_ + 4 * pc);
            CP_COMMIT();
            CP_WAIT(1);
        } else {
            CP_WAIT(0);
        }
        __syncthreads();

        if (active) {
            float acc0 = 0.f, acc1 = 0.f, acc2 = 0.f, acc3 = 0.f;
            const float4* wr = (const float4*)(wx_s + warp * A_);
            const float4* vr = (const float4*)v_s;
            const float*  ub = cur + 4 * lane;
#pragma unroll 8
            for (int a4 = 0; a4 < A_ / 4; a4++) {
                float4 w4 = wr[a4];
                float4 v4 = vr[a4];
#define DO(c, k) { \
                float4 uu = *(const float4*)(ub + (4 * a4 + k) * TJ); \
                float wc = w4.c, vc = v4.c; \
                acc0 = fmaf(tanh_fast(wc + uu.x), vc, acc0); \
                acc1 = fmaf(tanh_fast(wc + uu.y), vc, acc1); \
                acc2 = fmaf(tanh_fast(wc + uu.z), vc, acc2); \
                acc3 = fmaf(tanh_fast(wc + uu.w), vc, acc3); }
                DO(x, 0) DO(y, 1) DO(z, 2) DO(w, 3)
#undef DO
            }
            er[4 * t + 0] = acc0;
            er[4 * t + 1] = acc1;
            er[4 * t + 2] = acc2;
            er[4 * t + 3] = acc3;
        }
        __syncthreads();
    }

    float* slots = ux0;
    if (active) {
        float m = er[0];
#pragma unroll
        for (int k = 1; k < 4 * NT; k++) m = fmaxf(m, er[k]);
#pragma unroll
        for (int o = 16; o; o >>= 1) m = fmaxf(m, __shfl_xor_sync(0xffffffffu, m, o));
        float s = 0.f;
#pragma unroll
        for (int k = 0; k < 4 * NT; k++) {
            er[k] = __expf(er[k] - m);
            s += er[k];
        }
#pragma unroll
        for (int o = 16; o; o >>= 1) s += __shfl_xor_sync(0xffffffffu, s, o);
        float inv = 1.0f / s;
        float* orow = attn_out + (size_t)(b * S_ + i0 + warp) * S_;
        float* srow = slots + (size_t)warp * S_;
#pragma unroll
        for (int ti = 0; ti < NT; ti++) {
            float4 o = make_float4(er[4 * ti] * inv, er[4 * ti + 1] * inv,
                                   er[4 * ti + 2] * inv, er[4 * ti + 3] * inv);
            *(float4*)(orow + ti * TJ + 4 * lane) = o;
            *(float4*)(srow + ti * TJ + 4 * lane) = o;
        }
    }
    __syncthreads();

    for (int j = tid; j < S_; j += 512) {
        float s = 0.f;
        for (int r = 0; r < nr; r++) s += slots[(size_t)r * S_ + j];
        atomicAdd(&g_colsum[b * S_ + j], s);
    }
}

// ---------------- kernel 3: context[b,h] = sum_j colsum[b,j] * lstm[b,j,h] ----------------
__global__ __launch_bounds__(512) void context_kernel(
    const float* __restrict__ lstm, float* __restrict__ ctx)
{
    int b  = blockIdx.x >> 6;                  // 2 * 64 blocks
    int j0 = (blockIdx.x & 63) * 16;
    int h  = threadIdx.x;
    __shared__ float cs[16];
    if (threadIdx.x < 16) cs[threadIdx.x] = g_colsum[b * S_ + j0 + threadIdx.x];
    __syncthreads();
    float acc = 0.f;
    const float* lp = lstm + ((size_t)(b * S_ + j0)) * H_ + h;
#pragma unroll
    for (int j = 0; j < 16; j++) acc = fmaf(cs[j], lp[(size_t)j * H_], acc);
    atomicAdd(&ctx[b * H_ + h], acc);
}

// ---------------- launch: gemm0 -> [attn0 || gemm1] -> attn1 -> join -> context ----------------
extern "C" void kernel_launch(void* const* d_in, const int* in_sizes, int n_in,
                              void* d_out, int out_size)
{
    const float* lstm = (const float*)d_in[0];
    const float* w    = (const float*)d_in[1];
    const float* u    = (const float*)d_in[2];
    const float* v    = (const float*)d_in[3];
    float* out  = (float*)d_out;
    float* ctx  = out;                // (B,H) = 1024 floats first
    float* attn = out + B_ * H_;      // (B,S,S) = 2M floats after

    size_t smem = (size_t)(MAXR * A_ + 2 * A_ * TJ + A_) * sizeof(float); // ~139.8 KB
    cudaFuncSetAttribute(attn_e_kernel, cudaFuncAttributeMaxDynamicSharedMemorySize, (int)smem);

    // main stream: gemm b=0
    gemm_wxux_b<<<dim3(32, 4), 256>>>(lstm, w, u, ctx, 0);
    cudaEventRecord(hx.e_g0, 0);

    // side stream: attn b=0 after gemm0
    cudaStreamWaitEvent(hx.s2, hx.e_g0, 0);
    attn_e_kernel<<<CTAS_PER_B, 512, smem, hx.s2>>>(v, attn, 0);
    cudaEventRecord(hx.e_a0, hx.s2);

    // main stream: gemm b=1 (overlaps attn0), then attn b=1
    gemm_wxux_b<<<dim3(32, 4), 256>>>(lstm, w, u, ctx, 1);
    attn_e_kernel<<<CTAS_PER_B, 512, smem>>>(v, attn, 1);

    // join side stream, then context
    cudaStreamWaitEvent(0, hx.e_a0, 0);
    context_kernel<<<B_ * 64, 512>>>(lstm, ctx);
}

// round 6
// speedup vs baseline: 1.2345x; 1.2345x over previous
#include <cuda_runtime.h>
#include <cstdint>

// Shapes (fixed by the problem)
#define B_ 2
#define S_ 1024
#define H_ 512
#define A_ 128

#define CTAS_PER_B 74            // 148 attn CTAs total, 13-14 rows each
#define MAXR 16
#define TJ 128
#define NT 8                     // S_/TJ tiles

// ---------------- scratch (no allocation allowed) ----------------
__device__ float g_wx [B_ * S_ * A_];        // [m=b*S+s][a]  row-major (1 MB)
__device__ float g_uxt[B_ * A_ * S_];        // [b][a][s]     a-major / transposed (1 MB)
__device__ float g_colsum[B_ * S_];

__device__ __forceinline__ float tanh_fast(float x) {
    float y;
    asm("tanh.approx.f32 %0, %1;" : "=f"(y) : "f"(x));
    return y;
}

// packed half-precision tanh: 2 values through one MUFU op
__device__ __forceinline__ void tanh2_fast(float x0, float x1, float& t0, float& t1) {
    uint32_t h, h2;
    asm("cvt.rn.f16x2.f32 %0, %1, %2;" : "=r"(h) : "f"(x1), "f"(x0)); // lo=x0, hi=x1
    asm("tanh.approx.f16x2 %0, %1;" : "=r"(h2) : "r"(h));
    asm("{ .reg .b16 lo, hi;\n"
        "  mov.b32 {lo, hi}, %2;\n"
        "  cvt.f32.f16 %0, lo;\n"
        "  cvt.f32.f16 %1, hi; }"
        : "=f"(t0), "=f"(t1) : "r"(h2));
}

__device__ __forceinline__ void cp16(float* dst_smem, const float* src) {
    uint32_t d = (uint32_t)__cvta_generic_to_shared(dst_smem);
    asm volatile("cp.async.cg.shared.global [%0], [%1], 16;\n" :: "r"(d), "l"(src));
}
#define CP_COMMIT() asm volatile("cp.async.commit_group;\n")
#define CP_WAIT(N)  asm volatile("cp.async.wait_group %0;\n" :: "n"(N))

// ---------------- kernel 1: wx = lstm@w, uxt = (lstm@u)^T, fused zeroing ----------------
#define BM 64
#define BN 64
#define BK 16
__global__ __launch_bounds__(256) void gemm_wxux(
    const float* __restrict__ lstm, const float* __restrict__ w, const float* __restrict__ u,
    float* __restrict__ ctx)
{
    __shared__ float As[BK][BM];
    __shared__ float Bs[BK][BN];
    int tid = threadIdx.x;

    // fused zeroing of colsum + ctx (block (0,0) only)
    if (blockIdx.x == 0 && blockIdx.y == 0) {
        for (int t = tid; t < B_ * S_; t += 256) g_colsum[t] = 0.0f;
        for (int t = tid; t < B_ * H_; t += 256) ctx[t] = 0.0f;
    }

    int m0 = blockIdx.x * BM;
    int n0 = blockIdx.y * BN;                  // 0,64 -> w ; 128,192 -> u
    const float* bsrc = (n0 < A_) ? (w + n0) : (u + (n0 - A_));

    int tm = (tid >> 4) * 4;
    int tn = (tid & 15) * 4;
    int la_m = tid >> 2;
    int la_k = (tid & 3) * 4;
    int lb_k = tid >> 4;
    int lb_n = (tid & 15) * 4;

    float acc[4][4];
#pragma unroll
    for (int i = 0; i < 4; i++)
#pragma unroll
        for (int j = 0; j < 4; j++) acc[i][j] = 0.0f;

    for (int k0 = 0; k0 < H_; k0 += BK) {
        float4 av = *(const float4*)(lstm + (size_t)(m0 + la_m) * H_ + k0 + la_k);
        float4 bv = *(const float4*)(bsrc + (size_t)(k0 + lb_k) * A_ + lb_n);
        __syncthreads();
        As[la_k + 0][la_m] = av.x;
        As[la_k + 1][la_m] = av.y;
        As[la_k + 2][la_m] = av.z;
        As[la_k + 3][la_m] = av.w;
        *(float4*)&Bs[lb_k][lb_n] = bv;
        __syncthreads();
#pragma unroll
        for (int kk = 0; kk < BK; kk++) {
            float4 a4 = *(const float4*)&As[kk][tm];
            float4 b4 = *(const float4*)&Bs[kk][tn];
            float am[4] = {a4.x, a4.y, a4.z, a4.w};
            float bn[4] = {b4.x, b4.y, b4.z, b4.w};
#pragma unroll
            for (int i = 0; i < 4; i++)
#pragma unroll
                for (int j = 0; j < 4; j++) acc[i][j] = fmaf(am[i], bn[j], acc[i][j]);
        }
    }

    if (n0 < A_) {
#pragma unroll
        for (int i = 0; i < 4; i++) {
            float4 o = make_float4(acc[i][0], acc[i][1], acc[i][2], acc[i][3]);
            *(float4*)(g_wx + (size_t)(m0 + tm + i) * A_ + n0 + tn) = o;
        }
    } else {
        int b  = m0 / S_;
        int s0 = (m0 % S_) + tm;
        int a0 = (n0 - A_) + tn;
        float* base = g_uxt + (size_t)b * A_ * S_;
#pragma unroll
        for (int j = 0; j < 4; j++) {
            float4 o = make_float4(acc[0][j], acc[1][j], acc[2][j], acc[3][j]);
            *(float4*)(base + (size_t)(a0 + j) * S_ + s0) = o;
        }
    }
}

// ---------------- kernel 2: e = tanh-sum (f32 + f16x2 hybrid), reg softmax, attn + colsum ----
// dyn smem: wx_s[16][128] + ux double buffer 2*[128][TJ] + v_s[128]  ~ 139.8 KB
__global__ __launch_bounds__(512) void attn_e_kernel(
    const float* __restrict__ v, float* __restrict__ attn_out)
{
    extern __shared__ float sm[];
    float* wx_s = sm;                          // MAXR*128
    float* ux0  = wx_s + MAXR * A_;            // 128*TJ buffer 0
    float* ux1  = ux0 + A_ * TJ;               // 128*TJ buffer 1
    float* v_s  = ux1 + A_ * TJ;               // 128

    int tid  = threadIdx.x;
    int warp = tid >> 5;
    int lane = tid & 31;
    int blk  = blockIdx.x;                     // 148 blocks
    int b    = blk / CTAS_PER_B;
    int t_   = blk % CTAS_PER_B;
    int i0   = (S_ * t_) / CTAS_PER_B;
    int i1   = (S_ * (t_ + 1)) / CTAS_PER_B;
    int nr   = i1 - i0;                        // 13 or 14

    const float* uxt_b = g_uxt + (size_t)b * A_ * S_;
    int pa = tid >> 5, pc = tid & 31;          // prefetch coords: 8 rows per thread

#pragma unroll
    for (int k = 0; k < 8; k++)
        cp16(ux0 + (pa + 16 * k) * TJ + 4 * pc, uxt_b + (size_t)(pa + 16 * k) * S_ + 4 * pc);
    CP_COMMIT();

    for (int x = tid; x < nr * (A_ / 4); x += 512) {
        int r = x >> 5, c = x & 31;
        *(float4*)(wx_s + r * A_ + 4 * c) =
            *(const float4*)(g_wx + (size_t)(b * S_ + i0 + r) * A_ + 4 * c);
    }
    if (tid < 32) ((float4*)v_s)[tid] = ((const float4*)v)[tid];

    bool active = (warp < nr);
    float er[4 * NT];

#pragma unroll
    for (int t = 0; t < NT; t++) {
        float* cur = (t & 1) ? ux1 : ux0;
        if (t + 1 < NT) {
            float* nxt = ((t + 1) & 1) ? ux1 : ux0;
            const float* src = uxt_b + (size_t)(t + 1) * TJ;
#pragma unroll
            for (int k = 0; k < 8; k++)
                cp16(nxt + (pa + 16 * k) * TJ + 4 * pc, src + (size_t)(pa + 16 * k) * S_ + 4 * pc);
            CP_COMMIT();
            CP_WAIT(1);
        } else {
            CP_WAIT(0);
        }
        __syncthreads();

        if (active) {
            float acc0 = 0.f, acc1 = 0.f, acc2 = 0.f, acc3 = 0.f;
            const float4* wr = (const float4*)(wx_s + warp * A_);
            const float4* vr = (const float4*)v_s;
            const float*  ub = cur + 4 * lane;

            // ---- a in [0,64): f32 MUFU tanh ----
#pragma unroll 4
            for (int a4 = 0; a4 < 16; a4++) {
                float4 w4 = wr[a4];
                float4 v4 = vr[a4];
#define DO(c, k) { \
                float4 uu = *(const float4*)(ub + (4 * a4 + k) * TJ); \
                float wc = w4.c, vc = v4.c; \
                acc0 = fmaf(tanh_fast(wc + uu.x), vc, acc0); \
                acc1 = fmaf(tanh_fast(wc + uu.y), vc, acc1); \
                acc2 = fmaf(tanh_fast(wc + uu.z), vc, acc2); \
                acc3 = fmaf(tanh_fast(wc + uu.w), vc, acc3); }
                DO(x, 0) DO(y, 1) DO(z, 2) DO(w, 3)
#undef DO
            }

            // ---- a in [64,128): paired f16x2 tanh (2 per MUFU op) ----
#pragma unroll 4
            for (int a4 = 16; a4 < 32; a4++) {
                float4 w4 = wr[a4];
                float4 v4 = vr[a4];
                float4 uu0 = *(const float4*)(ub + (4 * a4 + 0) * TJ);
                float4 uu1 = *(const float4*)(ub + (4 * a4 + 1) * TJ);
                float4 uu2 = *(const float4*)(ub + (4 * a4 + 2) * TJ);
                float4 uu3 = *(const float4*)(ub + (4 * a4 + 3) * TJ);
#define DOH(c) { \
                float t0, t1, t2, t3; \
                tanh2_fast(w4.x + uu0.c, w4.y + uu1.c, t0, t1); \
                tanh2_fast(w4.z + uu2.c, w4.w + uu3.c, t2, t3); \
                float p; \
                p  = fmaf(t0, v4.x, fmaf(t1, v4.y, 0.f)); \
                p  = fmaf(t2, v4.z, fmaf(t3, v4.w, p)); \
                acc##c##_add(p); }
                // expand manually (no token-paste on acc names):
                {
                    float t0, t1, t2, t3;
                    tanh2_fast(w4.x + uu0.x, w4.y + uu1.x, t0, t1);
                    tanh2_fast(w4.z + uu2.x, w4.w + uu3.x, t2, t3);
                    acc0 = fmaf(t0, v4.x, acc0); acc0 = fmaf(t1, v4.y, acc0);
                    acc0 = fmaf(t2, v4.z, acc0); acc0 = fmaf(t3, v4.w, acc0);
                }
                {
                    float t0, t1, t2, t3;
                    tanh2_fast(w4.x + uu0.y, w4.y + uu1.y, t0, t1);
                    tanh2_fast(w4.z + uu2.y, w4.w + uu3.y, t2, t3);
                    acc1 = fmaf(t0, v4.x, acc1); acc1 = fmaf(t1, v4.y, acc1);
                    acc1 = fmaf(t2, v4.z, acc1); acc1 = fmaf(t3, v4.w, acc1);
                }
                {
                    float t0, t1, t2, t3;
                    tanh2_fast(w4.x + uu0.z, w4.y + uu1.z, t0, t1);
                    tanh2_fast(w4.z + uu2.z, w4.w + uu3.z, t2, t3);
                    acc2 = fmaf(t0, v4.x, acc2); acc2 = fmaf(t1, v4.y, acc2);
                    acc2 = fmaf(t2, v4.z, acc2); acc2 = fmaf(t3, v4.w, acc2);
                }
                {
                    float t0, t1, t2, t3;
                    tanh2_fast(w4.x + uu0.w, w4.y + uu1.w, t0, t1);
                    tanh2_fast(w4.z + uu2.w, w4.w + uu3.w, t2, t3);
                    acc3 = fmaf(t0, v4.x, acc3); acc3 = fmaf(t1, v4.y, acc3);
                    acc3 = fmaf(t2, v4.z, acc3); acc3 = fmaf(t3, v4.w, acc3);
                }
#undef DOH
            }

            er[4 * t + 0] = acc0;
            er[4 * t + 1] = acc1;
            er[4 * t + 2] = acc2;
            er[4 * t + 3] = acc3;
        }
        __syncthreads();
    }

    float* slots = ux0;
    if (active) {
        float m = er[0];
#pragma unroll
        for (int k = 1; k < 4 * NT; k++) m = fmaxf(m, er[k]);
#pragma unroll
        for (int o = 16; o; o >>= 1) m = fmaxf(m, __shfl_xor_sync(0xffffffffu, m, o));
        float s = 0.f;
#pragma unroll
        for (int k = 0; k < 4 * NT; k++) {
            er[k] = __expf(er[k] - m);
            s += er[k];
        }
#pragma unroll
        for (int o = 16; o; o >>= 1) s += __shfl_xor_sync(0xffffffffu, s, o);
        float inv = 1.0f / s;
        float* orow = attn_out + (size_t)(b * S_ + i0 + warp) * S_;
        float* srow = slots + (size_t)warp * S_;
#pragma unroll
        for (int ti = 0; ti < NT; ti++) {
            float4 o = make_float4(er[4 * ti] * inv, er[4 * ti + 1] * inv,
                                   er[4 * ti + 2] * inv, er[4 * ti + 3] * inv);
            *(float4*)(orow + ti * TJ + 4 * lane) = o;
            *(float4*)(srow + ti * TJ + 4 * lane) = o;
        }
    }
    __syncthreads();

    for (int j = tid; j < S_; j += 512) {
        float s = 0.f;
        for (int r = 0; r < nr; r++) s += slots[(size_t)r * S_ + j];
        atomicAdd(&g_colsum[b * S_ + j], s);
    }
}

// ---------------- kernel 3: context[b,h] = sum_j colsum[b,j] * lstm[b,j,h] ----------------
__global__ __launch_bounds__(512) void context_kernel(
    const float* __restrict__ lstm, float* __restrict__ ctx)
{
    int b  = blockIdx.x >> 6;                  // 2 * 64 blocks
    int j0 = (blockIdx.x & 63) * 16;
    int h  = threadIdx.x;
    __shared__ float cs[16];
    if (threadIdx.x < 16) cs[threadIdx.x] = g_colsum[b * S_ + j0 + threadIdx.x];
    __syncthreads();
    float acc = 0.f;
    const float* lp = lstm + ((size_t)(b * S_ + j0)) * H_ + h;
#pragma unroll
    for (int j = 0; j < 16; j++) acc = fmaf(cs[j], lp[(size_t)j * H_], acc);
    atomicAdd(&ctx[b * H_ + h], acc);
}

// ---------------- launch (single stream, deterministic) ----------------
extern "C" void kernel_launch(void* const* d_in, const int* in_sizes, int n_in,
                              void* d_out, int out_size)
{
    const float* lstm = (const float*)d_in[0];
    const float* w    = (const float*)d_in[1];
    const float* u    = (const float*)d_in[2];
    const float* v    = (const float*)d_in[3];
    float* out  = (float*)d_out;
    float* ctx  = out;                // (B,H) = 1024 floats first
    float* attn = out + B_ * H_;      // (B,S,S) = 2M floats after

    gemm_wxux<<<dim3(32, 4), 256>>>(lstm, w, u, ctx);

    size_t smem = (size_t)(MAXR * A_ + 2 * A_ * TJ + A_) * sizeof(float); // ~139.8 KB
    cudaFuncSetAttribute(attn_e_kernel, cudaFuncAttributeMaxDynamicSharedMemorySize, (int)smem);
    attn_e_kernel<<<B_ * CTAS_PER_B, 512, smem>>>(v, attn);

    context_kernel<<<B_ * 64, 512>>>(lstm, ctx);
}